// round 9
// baseline (speedup 1.0000x reference)
#include <cuda_runtime.h>
#include <cuda_fp16.h>
#include <math.h>
#include <stdint.h>

// ---------------- problem constants ----------------
#define DIMC    768
#define HEADS   12
#define HDIM    64
#define WS      14
#define NTOK    196
#define MLPD    3072
#define BATCH   4
#define IMGH    64
#define IMGW    64
#define NWIN    100
#define NROWS_WIN (NWIN*NTOK)        // 19600
#define NROWS_IMG (BATCH*IMGH*IMGW)  // 16384
#define SCALE_F 0.125f
#define EPS_F   1e-6f

// ---------------- scratch ----------------
__device__ float   g_xnhwc[BATCH*IMGH*IMGW*DIMC];
__device__ __half  g_xwin [NROWS_WIN*DIMC];
__device__ float   g_qkv  [NROWS_WIN*3*DIMC];
__device__ __half  g_attno[NROWS_WIN*DIMC];
__device__ float   g_proj [NROWS_WIN*DIMC];
__device__ float   g_x1   [NROWS_IMG*DIMC];
__device__ __half  g_yln  [NROWS_IMG*DIMC];
__device__ __half  g_h1   [NROWS_IMG*MLPD];
__device__ float   g_y2   [NROWS_IMG*DIMC];
// transposed weights (K-major B operands: Bt[n][k]), fp16
__device__ __half  g_qkvT [3*DIMC*DIMC];
__device__ __half  g_projT[DIMC*DIMC];
__device__ __half  g_fc1T [MLPD*DIMC];
__device__ __half  g_fc2T [DIMC*MLPD];

// ================= helpers =================
__device__ __forceinline__ uint32_t smem_u32(const void* p) {
    uint32_t a;
    asm("{ .reg .u64 t; cvta.to.shared.u64 t, %1; cvt.u32.u64 %0, t; }" : "=r"(a) : "l"(p));
    return a;
}
__device__ __forceinline__ void cp_async16(uint32_t dst, const void* src) {
    asm volatile("cp.async.cg.shared.global [%0], [%1], 16;" :: "r"(dst), "l"(src));
}
#define CP_COMMIT() asm volatile("cp.async.commit_group;" ::: "memory")
#define CP_WAIT(n)  asm volatile("cp.async.wait_group %0;" :: "n"(n) : "memory")

__device__ __forceinline__ void mma_f16(float* c, const uint32_t* a, const uint32_t* b) {
    asm volatile(
        "mma.sync.aligned.m16n8k16.row.col.f32.f16.f16.f32 "
        "{%0,%1,%2,%3}, {%4,%5,%6,%7}, {%8,%9}, {%0,%1,%2,%3};"
        : "+f"(c[0]), "+f"(c[1]), "+f"(c[2]), "+f"(c[3])
        : "r"(a[0]), "r"(a[1]), "r"(a[2]), "r"(a[3]), "r"(b[0]), "r"(b[1]));
}
__device__ __forceinline__ void ldmx4(uint32_t& r0, uint32_t& r1, uint32_t& r2, uint32_t& r3,
                                      uint32_t addr) {
    asm volatile("ldmatrix.sync.aligned.m8n8.x4.shared.b16 {%0,%1,%2,%3}, [%4];"
        : "=r"(r0), "=r"(r1), "=r"(r2), "=r"(r3) : "r"(addr));
}

// ================= fp16 mma.sync GEMM: C[M,N] = A[M,K] @ Bt[N,K]^T + bias ======
// 128x128x32 CTA tile, 8 warps (4Mx2N), warp tile 32x64.
// 3-stage cp.async pipeline; ldmatrix.x4 fragment loads.
#define BM 128
#define BN 128
#define BKE 32                     // K elements (fp16) per chunk
#define LDW 20                     // padded words per row (16 data + 4 pad)
#define TBUF (BM*LDW)              // words per tile buffer
#define NST 3
#define GEMM_SMEM ((2*NST*TBUF + 128) * 4)

__global__ void __launch_bounds__(256, 2)
k_mma_gemm(const __half* __restrict__ A, const __half* __restrict__ Bt,
           const float* __restrict__ bias, void* __restrict__ Cout,
           int M, int N, int K, int act, int outf16) {
    extern __shared__ float sm[];
    uint32_t* As = (uint32_t*)sm;            // [3][128][20] words
    uint32_t* Bs = As + NST*TBUF;            // [3][128][20]
    float* sbias = sm + 2*NST*TBUF;          // [128]

    int tid = threadIdx.x, lane = tid & 31, wid = tid >> 5;
    int wm = wid >> 1, wn = wid & 1;         // 4 x 2 warp grid, 32x64 tiles
    int m0 = blockIdx.y * BM, n0 = blockIdx.x * BN;

    if (tid < 128) sbias[tid] = bias[n0 + tid];

    auto load_tile = [&](int kc, int slot) {
        int k0 = kc * BKE;
        uint32_t* abuf = As + slot * TBUF;
        uint32_t* bbuf = Bs + slot * TBUF;
        #pragma unroll
        for (int it = 0; it < 2; it++) {      // 512 16B-chunks per tile / 256 threads
            int idx = tid + it * 256;         // 0..511
            int r = idx >> 2, c = idx & 3;    // row 0..127, 16B chunk (8 halves)
            int ar = m0 + r;
            const __half* asrc = A + (long)(ar < M ? ar : M - 1) * K + k0 + c * 8;
            cp_async16(smem_u32(abuf + r * LDW + c * 4), asrc);
            const __half* bsrc = Bt + (long)(n0 + r) * K + k0 + c * 8;
            cp_async16(smem_u32(bbuf + r * LDW + c * 4), bsrc);
        }
    };

    // ldmatrix per-lane word offsets (without ks / slot)
    int m8 = lane >> 3, r8 = lane & 7;
    uint32_t aoff[2], boff[4];
    #pragma unroll
    for (int mt = 0; mt < 2; mt++)
        aoff[mt] = (uint32_t)((wm * 32 + mt * 16 + (m8 & 1) * 8 + r8) * LDW + (m8 >> 1) * 4);
    #pragma unroll
    for (int p = 0; p < 4; p++)
        boff[p] = (uint32_t)((wn * 64 + p * 16 + (m8 >> 1) * 8 + r8) * LDW + (m8 & 1) * 4);
    uint32_t a_base = smem_u32(As);
    uint32_t b_base = smem_u32(Bs);

    float acc[2][8][4];
    #pragma unroll
    for (int mt = 0; mt < 2; mt++)
        #pragma unroll
        for (int nt = 0; nt < 8; nt++)
            #pragma unroll
            for (int j = 0; j < 4; j++) acc[mt][nt][j] = 0.f;

    const int NKC = K / BKE;
    load_tile(0, 0); CP_COMMIT();
    load_tile(1, 1); CP_COMMIT();
    for (int i = 0; i < NKC; i++) {
        int slot = i % NST;
        CP_WAIT(1);                 // group i complete
        __syncthreads();
        if (i + 2 < NKC) load_tile(i + 2, (i + 2) % NST);
        CP_COMMIT();                // always commit (possibly empty) to keep count exact
        uint32_t ab = a_base + slot * (TBUF * 4);
        uint32_t bb = b_base + slot * (TBUF * 4);
        #pragma unroll
        for (int ks = 0; ks < 2; ks++) {
            uint32_t af[2][4], bf[8][2];
            #pragma unroll
            for (int mt = 0; mt < 2; mt++)
                ldmx4(af[mt][0], af[mt][1], af[mt][2], af[mt][3],
                      ab + (aoff[mt] + ks * 8) * 4);
            #pragma unroll
            for (int p = 0; p < 4; p++)
                ldmx4(bf[2*p][0], bf[2*p][1], bf[2*p+1][0], bf[2*p+1][1],
                      bb + (boff[p] + ks * 8) * 4);
            #pragma unroll
            for (int mt = 0; mt < 2; mt++)
                #pragma unroll
                for (int nt = 0; nt < 8; nt++)
                    mma_f16(acc[mt][nt], af[mt], bf[nt]);
        }
    }

    // epilogue: bias + optional exact GELU; fp32 or fp16 stores
    int rb = m0 + wm * 32 + (lane >> 2);
    int cb = wn * 64 + 2 * (lane & 3);
    #pragma unroll
    for (int mt = 0; mt < 2; mt++) {
        int r0 = rb + mt * 16, r1 = r0 + 8;
        #pragma unroll
        for (int nt = 0; nt < 8; nt++) {
            int cc = cb + nt * 8;
            float v0 = acc[mt][nt][0] + sbias[cc];
            float v1 = acc[mt][nt][1] + sbias[cc + 1];
            float v2 = acc[mt][nt][2] + sbias[cc];
            float v3 = acc[mt][nt][3] + sbias[cc + 1];
            if (act == 1) {
                v0 = 0.5f * v0 * (1.0f + erff(v0 * 0.70710678118654752f));
                v1 = 0.5f * v1 * (1.0f + erff(v1 * 0.70710678118654752f));
                v2 = 0.5f * v2 * (1.0f + erff(v2 * 0.70710678118654752f));
                v3 = 0.5f * v3 * (1.0f + erff(v3 * 0.70710678118654752f));
            }
            if (outf16) {
                __half* C = (__half*)Cout;
                if (r0 < M) *(__half2*)(C + (long)r0 * N + n0 + cc) = __floats2half2_rn(v0, v1);
                if (r1 < M) *(__half2*)(C + (long)r1 * N + n0 + cc) = __floats2half2_rn(v2, v3);
            } else {
                float* C = (float*)Cout;
                if (r0 < M) *(float2*)(C + (long)r0 * N + n0 + cc) = make_float2(v0, v1);
                if (r1 < M) *(float2*)(C + (long)r1 * N + n0 + cc) = make_float2(v2, v3);
            }
        }
    }
}

// ---------------- NCHW -> NHWC transpose ----------------
__global__ void k_transpose_in(const float* __restrict__ in, float* __restrict__ out) {
    __shared__ float tile[32][33];
    int b = blockIdx.z, c0 = blockIdx.y * 32, s0 = blockIdx.x * 32;
    const float* ib = in + (long)b * DIMC * 4096;
    float* ob = out + (long)b * 4096 * DIMC;
    int x = threadIdx.x, y = threadIdx.y;
    #pragma unroll
    for (int i = 0; i < 32; i += 8)
        tile[y + i][x] = ib[(long)(c0 + y + i) * 4096 + s0 + x];
    __syncthreads();
    #pragma unroll
    for (int i = 0; i < 32; i += 8)
        ob[(long)(s0 + y + i) * DIMC + c0 + x] = tile[x][y + i];
}

// ---------------- weight transpose to fp16: in(R,C) -> out(C,R) ----------------
__global__ void k_transpose_w(const float* __restrict__ in, __half* __restrict__ out,
                              int R, int C) {
    __shared__ float tile[32][33];
    int r0 = blockIdx.y * 32, c0 = blockIdx.x * 32;
    int x = threadIdx.x, y = threadIdx.y;
    #pragma unroll
    for (int i = 0; i < 32; i += 8)
        tile[y + i][x] = in[(long)(r0 + y + i) * C + c0 + x];
    __syncthreads();
    #pragma unroll
    for (int i = 0; i < 32; i += 8)
        out[(long)(c0 + y + i) * R + r0 + x] = __float2half_rn(tile[x][y + i]);
}

// ---------------- block reduction ----------------
__device__ __forceinline__ float block_sum_256(float v, float* red) {
    int tid = threadIdx.x;
    #pragma unroll
    for (int o = 16; o > 0; o >>= 1) v += __shfl_xor_sync(0xffffffffu, v, o);
    if ((tid & 31) == 0) red[tid >> 5] = v;
    __syncthreads();
    float r = 0.f;
    if (tid < 8) {
        r = red[tid];
        #pragma unroll
        for (int o = 4; o > 0; o >>= 1) r += __shfl_xor_sync(0xffu, r, o);
        if (tid == 0) red[0] = r;
    }
    __syncthreads();
    r = red[0];
    __syncthreads();
    return r;
}

// ---------------- LN1 + window partition (fp16 output) ----------------
__global__ void k_ln1_window(const float* __restrict__ xnhwc,
                             const float* __restrict__ w, const float* __restrict__ bs,
                             __half* __restrict__ xwin) {
    __shared__ float red[8];
    int idx = blockIdx.x;
    int win = idx / NTOK, t = idx % NTOK;
    int b = win / 25, wrem = win % 25;
    int gr = (wrem / 5) * WS + t / WS;
    int gc = (wrem % 5) * WS + t % WS;
    __half* orow = xwin + (long)idx * DIMC;
    int tid = threadIdx.x;
    if (gr >= IMGH || gc >= IMGW) {
        for (int c = tid; c < DIMC; c += 256) orow[c] = __float2half_rn(0.f);
        return;
    }
    const float* irow = xnhwc + ((long)b * 4096 + gr * IMGW + gc) * DIMC;
    float v[3], s = 0.f, s2 = 0.f;
    #pragma unroll
    for (int i = 0; i < 3; i++) { float x = irow[tid + i * 256]; v[i] = x; s += x; s2 += x * x; }
    float tot = block_sum_256(s, red);
    float tot2 = block_sum_256(s2, red);
    float mu = tot * (1.f / DIMC);
    float rstd = rsqrtf(tot2 * (1.f / DIMC) - mu * mu + EPS_F);
    #pragma unroll
    for (int i = 0; i < 3; i++) {
        int c = tid + i * 256;
        orow[c] = __float2half_rn((v[i] - mu) * rstd * w[c] + bs[c]);
    }
}

// ---------------- fused: window unpartition + residual + LN2 ----------------
__global__ void k_scatter_ln2(const float* __restrict__ xnhwc, const float* __restrict__ proj,
                              const float* __restrict__ w, const float* __restrict__ bs,
                              float* __restrict__ x1, __half* __restrict__ yln) {
    __shared__ float red[8];
    int row = blockIdx.x;
    int b = row >> 12, sp = row & 4095;
    int r = sp >> 6, cw = sp & 63;
    int win = b * 25 + (r / WS) * 5 + (cw / WS);
    int t = (r % WS) * WS + (cw % WS);
    const float* prow = proj + ((long)win * NTOK + t) * DIMC;
    const float* xrow = xnhwc + (long)row * DIMC;
    float* orow = x1 + (long)row * DIMC;
    __half* lrow = yln + (long)row * DIMC;
    int tid = threadIdx.x;
    float v[3], s = 0.f, s2 = 0.f;
    #pragma unroll
    for (int i = 0; i < 3; i++) {
        int c = tid + i * 256;
        float x = xrow[c] + prow[c];
        orow[c] = x;
        v[i] = x; s += x; s2 += x * x;
    }
    float tot = block_sum_256(s, red);
    float tot2 = block_sum_256(s2, red);
    float mu = tot * (1.f / DIMC);
    float rstd = rsqrtf(tot2 * (1.f / DIMC) - mu * mu + EPS_F);
    #pragma unroll
    for (int i = 0; i < 3; i++) {
        int c = tid + i * 256;
        lrow[c] = __float2half_rn((v[i] - mu) * rstd * w[c] + bs[c]);
    }
}

// ---------------- fused windowed attention: 4 threads per query --------------
#define RELSTRIDE 65
#define QSTRIDE   17
#define ATTN_THREADS 784           // 4 * 196, zero idle threads
#define ATTN_SMEM ((2*NTOK*HDIM + 2*27*RELSTRIDE + 2*NTOK*QSTRIDE) * sizeof(float))

__global__ void __launch_bounds__(ATTN_THREADS, 1)
k_attn(const float* __restrict__ qkv,
       const float* __restrict__ rel_pos_h,
       const float* __restrict__ rel_pos_w,
       __half* __restrict__ attnout) {
    extern __shared__ float smn[];
    float* Ks   = smn;
    float* Vs   = smn + NTOK * HDIM;
    float* RHsm = smn + 2 * NTOK * HDIM;
    float* RWsm = RHsm + 27 * RELSTRIDE;
    float* RHq  = RWsm + 27 * RELSTRIDE;
    float* RWq  = RHq + NTOK * QSTRIDE;

    int bidx = blockIdx.x;
    int win = bidx / HEADS, head = bidx % HEADS;
    int tid = threadIdx.x;
    const float* qkv_win = qkv + (long)win * NTOK * (3 * DIMC);

    for (int i = tid; i < NTOK * HDIM; i += ATTN_THREADS) {
        int t = i >> 6, d = i & 63;
        long base = (long)t * (3 * DIMC) + head * HDIM + d;
        Ks[i] = qkv_win[base + DIMC];
        Vs[i] = qkv_win[base + 2 * DIMC];
    }
    for (int i = tid; i < 27 * HDIM; i += ATTN_THREADS) {
        int r = i >> 6, d = i & 63;
        RHsm[r * RELSTRIDE + d] = rel_pos_h[i];
        RWsm[r * RELSTRIDE + d] = rel_pos_w[i];
    }
    __syncthreads();

    int q = tid >> 2, quarter = tid & 3;          // 4 threads per query, 16 dims each
    int qh = q / WS, qw = q % WS;
    unsigned pmask = (tid >= 768) ? 0x0000ffffu : 0xffffffffu;   // last warp has 16 lanes

    float qv[16];
    {
        const float* qp = qkv_win + (long)q * (3 * DIMC) + head * HDIM + quarter * 16;
        #pragma unroll
        for (int d = 0; d < 16; d++) qv[d] = qp[d];
    }

    // per-query rel-pos biases into smem (quad-reduced via shfl)
    #pragma unroll
    for (int kh = 0; kh < WS; kh++) {
        const float* ph = &RHsm[(qh - kh + WS - 1) * RELSTRIDE + quarter * 16];
        const float* pw = &RWsm[(qw - kh + WS - 1) * RELSTRIDE + quarter * 16];
        float sh = 0.f, sw = 0.f;
        #pragma unroll
        for (int d = 0; d < 16; d++) { sh = fmaf(qv[d], ph[d], sh); sw = fmaf(qv[d], pw[d], sw); }
        sh += __shfl_xor_sync(pmask, sh, 1);
        sh += __shfl_xor_sync(pmask, sh, 2);
        sw += __shfl_xor_sync(pmask, sw, 1);
        sw += __shfl_xor_sync(pmask, sw, 2);
        if (quarter == 0) { RHq[q * QSTRIDE + kh] = sh; RWq[q * QSTRIDE + kh] = sw; }
    }
    #pragma unroll
    for (int d = 0; d < 16; d++) qv[d] *= SCALE_F;
    __syncthreads();

    float m = -1e30f, l = 0.f;
    float acc[16];
    #pragma unroll
    for (int d = 0; d < 16; d++) acc[d] = 0.f;

    const float* rhq = RHq + q * QSTRIDE;
    const float* rwq = RWq + q * QSTRIDE;
    const float* KsH = Ks + quarter * 16;
    const float* VsH = Vs + quarter * 16;

    int kh = 0, kw = 0;
    for (int k = 0; k < NTOK; k++) {
        float part = 0.f;
        const float4* kp = (const float4*)(KsH + k * HDIM);
        #pragma unroll
        for (int d4 = 0; d4 < 4; d4++) {
            float4 kv = kp[d4];
            part = fmaf(qv[d4*4+0], kv.x, part); part = fmaf(qv[d4*4+1], kv.y, part);
            part = fmaf(qv[d4*4+2], kv.z, part); part = fmaf(qv[d4*4+3], kv.w, part);
        }
        part += __shfl_xor_sync(pmask, part, 1);
        part += __shfl_xor_sync(pmask, part, 2);
        float s = rhq[kh] + rwq[kw] + part;
        if (++kw == WS) { kw = 0; kh++; }
        float p;
        if (s > m) {
            float corr = __expf(m - s);
            l *= corr;
            #pragma unroll
            for (int d = 0; d < 16; d++) acc[d] *= corr;
            m = s; p = 1.f;
        } else {
            p = __expf(s - m);
        }
        l += p;
        const float4* vp = (const float4*)(VsH + k * HDIM);
        #pragma unroll
        for (int d4 = 0; d4 < 4; d4++) {
            float4 vv = vp[d4];
            acc[d4*4+0] = fmaf(p, vv.x, acc[d4*4+0]);
            acc[d4*4+1] = fmaf(p, vv.y, acc[d4*4+1]);
            acc[d4*4+2] = fmaf(p, vv.z, acc[d4*4+2]);
            acc[d4*4+3] = fmaf(p, vv.w, acc[d4*4+3]);
        }
    }
    float inv = 1.f / l;
    __half* op = attnout + ((long)win * NTOK + q) * DIMC + head * HDIM + quarter * 16;
    #pragma unroll
    for (int d = 0; d < 16; d++) op[d] = __float2half_rn(acc[d] * inv);
}

// ---------------- final: x1 + mlp_out, NHWC -> NCHW ----------------
__global__ void k_final(const float* __restrict__ x1, const float* __restrict__ y2,
                        float* __restrict__ out) {
    __shared__ float tile[32][33];
    int b = blockIdx.z, s0 = blockIdx.x * 32, c0 = blockIdx.y * 32;
    int x = threadIdx.x, y = threadIdx.y;
    #pragma unroll
    for (int i = 0; i < 32; i += 8) {
        long row = (long)b * 4096 + s0 + y + i;
        tile[y + i][x] = x1[row * DIMC + c0 + x] + y2[row * DIMC + c0 + x];
    }
    __syncthreads();
    #pragma unroll
    for (int i = 0; i < 32; i += 8)
        out[((long)b * DIMC + c0 + y + i) * 4096 + s0 + x] = tile[x][y + i];
}

// ---------------- launcher ----------------
extern "C" void kernel_launch(void* const* d_in, const int* in_sizes, int n_in,
                              void* d_out, int out_size) {
    const float* hidden = (const float*)d_in[0];
    const float* ln1_w = (const float*)d_in[1];
    const float* ln1_b = (const float*)d_in[2];
    const float* qkv_w = (const float*)d_in[3];
    const float* qkv_b = (const float*)d_in[4];
    const float* proj_w = (const float*)d_in[5];
    const float* proj_b = (const float*)d_in[6];
    const float* relh = (const float*)d_in[7];
    const float* relw = (const float*)d_in[8];
    const float* ln2_w = (const float*)d_in[9];
    const float* ln2_b = (const float*)d_in[10];
    const float* fc1_w = (const float*)d_in[11];
    const float* fc1_b = (const float*)d_in[12];
    const float* fc2_w = (const float*)d_in[13];
    const float* fc2_b = (const float*)d_in[14];
    float* out = (float*)d_out;

    float *xnhwc, *qkv, *proj, *x1, *y2;
    __half *xwin, *attno, *yln, *h1, *qkvT, *projT, *fc1T, *fc2T;
    cudaGetSymbolAddress((void**)&xnhwc, g_xnhwc);
    cudaGetSymbolAddress((void**)&xwin, g_xwin);
    cudaGetSymbolAddress((void**)&qkv, g_qkv);
    cudaGetSymbolAddress((void**)&attno, g_attno);
    cudaGetSymbolAddress((void**)&proj, g_proj);
    cudaGetSymbolAddress((void**)&x1, g_x1);
    cudaGetSymbolAddress((void**)&yln, g_yln);
    cudaGetSymbolAddress((void**)&h1, g_h1);
    cudaGetSymbolAddress((void**)&y2, g_y2);
    cudaGetSymbolAddress((void**)&qkvT, g_qkvT);
    cudaGetSymbolAddress((void**)&projT, g_projT);
    cudaGetSymbolAddress((void**)&fc1T, g_fc1T);
    cudaGetSymbolAddress((void**)&fc2T, g_fc2T);

    cudaFuncSetAttribute(k_attn, cudaFuncAttributeMaxDynamicSharedMemorySize, (int)ATTN_SMEM);
    cudaFuncSetAttribute(k_mma_gemm, cudaFuncAttributeMaxDynamicSharedMemorySize, GEMM_SMEM);

    dim3 tb(32, 8);
    // weight transposes -> fp16 K-major
    k_transpose_w<<<dim3(3 * DIMC / 32, DIMC / 32), tb>>>(qkv_w, qkvT, DIMC, 3 * DIMC);
    k_transpose_w<<<dim3(DIMC / 32, DIMC / 32), tb>>>(proj_w, projT, DIMC, DIMC);
    k_transpose_w<<<dim3(MLPD / 32, DIMC / 32), tb>>>(fc1_w, fc1T, DIMC, MLPD);
    k_transpose_w<<<dim3(DIMC / 32, MLPD / 32), tb>>>(fc2_w, fc2T, MLPD, DIMC);

    // 1) NCHW -> NHWC
    k_transpose_in<<<dim3(128, 24, BATCH), tb>>>(hidden, xnhwc);
    // 2) LN1 + window partition (fp16)
    k_ln1_window<<<NROWS_WIN, 256>>>(xnhwc, ln1_w, ln1_b, xwin);
    // 3) QKV: (19600,768) x (768,2304) -> fp32
    k_mma_gemm<<<dim3(3 * DIMC / 128, (NROWS_WIN + 127) / 128), 256, GEMM_SMEM>>>(
        xwin, qkvT, qkv_b, qkv, NROWS_WIN, 3 * DIMC, DIMC, 0, 0);
    // 4) attention (fp32 in, fp16 out)
    k_attn<<<NWIN * HEADS, ATTN_THREADS, ATTN_SMEM>>>(qkv, relh, relw, attno);
    // 5) proj: (19600,768) x (768,768) -> fp32
    k_mma_gemm<<<dim3(DIMC / 128, (NROWS_WIN + 127) / 128), 256, GEMM_SMEM>>>(
        attno, projT, proj_b, proj, NROWS_WIN, DIMC, DIMC, 0, 0);
    // 6) unpartition + residual + LN2 (x1 fp32, yln fp16)
    k_scatter_ln2<<<NROWS_IMG, 256>>>(xnhwc, proj, ln2_w, ln2_b, x1, yln);
    // 7) FC1 + GELU: (16384,768) x (768,3072) -> fp16
    k_mma_gemm<<<dim3(MLPD / 128, NROWS_IMG / 128), 256, GEMM_SMEM>>>(
        yln, fc1T, fc1_b, h1, NROWS_IMG, MLPD, DIMC, 1, 1);
    // 8) FC2: (16384,3072) x (3072,768) -> fp32
    k_mma_gemm<<<dim3(DIMC / 128, NROWS_IMG / 128), 256, GEMM_SMEM>>>(
        h1, fc2T, fc2_b, y2, NROWS_IMG, DIMC, MLPD, 0, 0);
    // 9) residual + NHWC -> NCHW
    k_final<<<dim3(128, 24, BATCH), tb>>>(x1, y2, out);
}

// round 10
// speedup vs baseline: 1.2986x; 1.2986x over previous
#include <cuda_runtime.h>
#include <cuda_fp16.h>
#include <math.h>
#include <stdint.h>

// ---------------- problem constants ----------------
#define DIMC    768
#define HEADS   12
#define HDIM    64
#define WS      14
#define NTOK    196
#define MLPD    3072
#define BATCH   4
#define IMGH    64
#define IMGW    64
#define NWIN    100
#define NROWS_WIN (NWIN*NTOK)        // 19600
#define NROWS_IMG (BATCH*IMGH*IMGW)  // 16384
#define SCALE_F 0.125f
#define EPS_F   1e-6f

// ---------------- scratch ----------------
__device__ float   g_xnhwc[BATCH*IMGH*IMGW*DIMC];
__device__ __half  g_xwin [NROWS_WIN*DIMC];
__device__ float   g_qkv  [NROWS_WIN*3*DIMC];
__device__ __half  g_attno[NROWS_WIN*DIMC];
__device__ float   g_proj [NROWS_WIN*DIMC];
__device__ float   g_x1   [NROWS_IMG*DIMC];
__device__ __half  g_yln  [NROWS_IMG*DIMC];
__device__ __half  g_h1   [NROWS_IMG*MLPD];
__device__ float   g_y2   [NROWS_IMG*DIMC];
// transposed weights (K-major B operands: Bt[n][k]), fp16
__device__ __half  g_qkvT [3*DIMC*DIMC];
__device__ __half  g_projT[DIMC*DIMC];
__device__ __half  g_fc1T [MLPD*DIMC];
__device__ __half  g_fc2T [DIMC*MLPD];

// ================= helpers =================
__device__ __forceinline__ uint32_t smem_u32(const void* p) {
    uint32_t a;
    asm("{ .reg .u64 t; cvta.to.shared.u64 t, %1; cvt.u32.u64 %0, t; }" : "=r"(a) : "l"(p));
    return a;
}
__device__ __forceinline__ void cp_async16(uint32_t dst, const void* src) {
    asm volatile("cp.async.cg.shared.global [%0], [%1], 16;" :: "r"(dst), "l"(src));
}
#define CP_COMMIT() asm volatile("cp.async.commit_group;" ::: "memory")
#define CP_WAIT(n)  asm volatile("cp.async.wait_group %0;" :: "n"(n) : "memory")

__device__ __forceinline__ void mma_f16(float* c, const uint32_t* a, const uint32_t* b) {
    asm volatile(
        "mma.sync.aligned.m16n8k16.row.col.f32.f16.f16.f32 "
        "{%0,%1,%2,%3}, {%4,%5,%6,%7}, {%8,%9}, {%0,%1,%2,%3};"
        : "+f"(c[0]), "+f"(c[1]), "+f"(c[2]), "+f"(c[3])
        : "r"(a[0]), "r"(a[1]), "r"(a[2]), "r"(a[3]), "r"(b[0]), "r"(b[1]));
}
__device__ __forceinline__ void ldmx4(uint32_t& r0, uint32_t& r1, uint32_t& r2, uint32_t& r3,
                                      uint32_t addr) {
    asm volatile("ldmatrix.sync.aligned.m8n8.x4.shared.b16 {%0,%1,%2,%3}, [%4];"
        : "=r"(r0), "=r"(r1), "=r"(r2), "=r"(r3) : "r"(addr));
}

// ================= fp16 mma.sync GEMM: C[M,N] = A[M,K] @ Bt[N,K]^T + bias ======
// 128x128x32 CTA tile, 8 warps (4Mx2N), warp tile 32x64.
// R8 double-buffered cp.async pipeline; ldmatrix.x4 fragment loads (R9-verified).
#define BM 128
#define BN 128
#define BKE 32                     // K elements (fp16) per chunk
#define LDW 20                     // padded words per row (16 data + 4 pad)
#define TBUF (BM*LDW)              // words per tile buffer
#define GEMM_SMEM ((4*TBUF + 128) * 4)

__global__ void __launch_bounds__(256, 2)
k_mma_gemm(const __half* __restrict__ A, const __half* __restrict__ Bt,
           const float* __restrict__ bias, void* __restrict__ Cout,
           int M, int N, int K, int act, int outf16) {
    extern __shared__ float sm[];
    uint32_t* As = (uint32_t*)sm;            // [2][128][20] words
    uint32_t* Bs = As + 2*TBUF;              // [2][128][20]
    float* sbias = sm + 4*TBUF;              // [128]

    int tid = threadIdx.x, lane = tid & 31, wid = tid >> 5;
    int wm = wid >> 1, wn = wid & 1;         // 4 x 2 warp grid, 32x64 tiles
    int m0 = blockIdx.y * BM, n0 = blockIdx.x * BN;

    if (tid < 128) sbias[tid] = bias[n0 + tid];

    auto load_tile = [&](int kc, int bsel) {
        int k0 = kc * BKE;
        uint32_t* abuf = As + bsel * TBUF;
        uint32_t* bbuf = Bs + bsel * TBUF;
        #pragma unroll
        for (int it = 0; it < 2; it++) {      // 512 16B-chunks per tile / 256 threads
            int idx = tid + it * 256;         // 0..511
            int r = idx >> 2, c = idx & 3;    // row 0..127, 16B chunk (8 halves)
            int ar = m0 + r;
            const __half* asrc = A + (long)(ar < M ? ar : M - 1) * K + k0 + c * 8;
            cp_async16(smem_u32(abuf + r * LDW + c * 4), asrc);
            const __half* bsrc = Bt + (long)(n0 + r) * K + k0 + c * 8;
            cp_async16(smem_u32(bbuf + r * LDW + c * 4), bsrc);
        }
        CP_COMMIT();
    };

    // ldmatrix per-lane word offsets (without ks / buffer)
    int m8 = lane >> 3, r8 = lane & 7;
    uint32_t aoff[2], boff[4];
    #pragma unroll
    for (int mt = 0; mt < 2; mt++)
        aoff[mt] = (uint32_t)((wm * 32 + mt * 16 + (m8 & 1) * 8 + r8) * LDW + (m8 >> 1) * 4);
    #pragma unroll
    for (int p = 0; p < 4; p++)
        boff[p] = (uint32_t)((wn * 64 + p * 16 + (m8 >> 1) * 8 + r8) * LDW + (m8 & 1) * 4);
    uint32_t a_base = smem_u32(As);
    uint32_t b_base = smem_u32(Bs);

    float acc[2][8][4];
    #pragma unroll
    for (int mt = 0; mt < 2; mt++)
        #pragma unroll
        for (int nt = 0; nt < 8; nt++)
            #pragma unroll
            for (int j = 0; j < 4; j++) acc[mt][nt][j] = 0.f;

    const int NKC = K / BKE;
    load_tile(0, 0);
    for (int i = 0; i < NKC; i++) {
        int cur = i & 1;
        if (i + 1 < NKC) { load_tile(i + 1, cur ^ 1); CP_WAIT(1); }
        else             { CP_WAIT(0); }
        __syncthreads();
        uint32_t ab = a_base + cur * (TBUF * 4);
        uint32_t bb = b_base + cur * (TBUF * 4);
        #pragma unroll
        for (int ks = 0; ks < 2; ks++) {      // two K=16 steps per 32-elt chunk
            uint32_t af[2][4], bf[8][2];
            #pragma unroll
            for (int mt = 0; mt < 2; mt++)
                ldmx4(af[mt][0], af[mt][1], af[mt][2], af[mt][3],
                      ab + (aoff[mt] + ks * 8) * 4);
            #pragma unroll
            for (int p = 0; p < 4; p++)
                ldmx4(bf[2*p][0], bf[2*p][1], bf[2*p+1][0], bf[2*p+1][1],
                      bb + (boff[p] + ks * 8) * 4);
            #pragma unroll
            for (int mt = 0; mt < 2; mt++)
                #pragma unroll
                for (int nt = 0; nt < 8; nt++)
                    mma_f16(acc[mt][nt], af[mt], bf[nt]);
        }
        __syncthreads();
    }

    // epilogue: bias + optional exact GELU; fp32 or fp16 stores
    int rb = m0 + wm * 32 + (lane >> 2);
    int cb = wn * 64 + 2 * (lane & 3);
    #pragma unroll
    for (int mt = 0; mt < 2; mt++) {
        int r0 = rb + mt * 16, r1 = r0 + 8;
        #pragma unroll
        for (int nt = 0; nt < 8; nt++) {
            int cc = cb + nt * 8;
            float v0 = acc[mt][nt][0] + sbias[cc];
            float v1 = acc[mt][nt][1] + sbias[cc + 1];
            float v2 = acc[mt][nt][2] + sbias[cc];
            float v3 = acc[mt][nt][3] + sbias[cc + 1];
            if (act == 1) {
                v0 = 0.5f * v0 * (1.0f + erff(v0 * 0.70710678118654752f));
                v1 = 0.5f * v1 * (1.0f + erff(v1 * 0.70710678118654752f));
                v2 = 0.5f * v2 * (1.0f + erff(v2 * 0.70710678118654752f));
                v3 = 0.5f * v3 * (1.0f + erff(v3 * 0.70710678118654752f));
            }
            if (outf16) {
                __half* C = (__half*)Cout;
                if (r0 < M) *(__half2*)(C + (long)r0 * N + n0 + cc) = __floats2half2_rn(v0, v1);
                if (r1 < M) *(__half2*)(C + (long)r1 * N + n0 + cc) = __floats2half2_rn(v2, v3);
            } else {
                float* C = (float*)Cout;
                if (r0 < M) *(float2*)(C + (long)r0 * N + n0 + cc) = make_float2(v0, v1);
                if (r1 < M) *(float2*)(C + (long)r1 * N + n0 + cc) = make_float2(v2, v3);
            }
        }
    }
}

// ---------------- NCHW -> NHWC transpose ----------------
__global__ void k_transpose_in(const float* __restrict__ in, float* __restrict__ out) {
    __shared__ float tile[32][33];
    int b = blockIdx.z, c0 = blockIdx.y * 32, s0 = blockIdx.x * 32;
    const float* ib = in + (long)b * DIMC * 4096;
    float* ob = out + (long)b * 4096 * DIMC;
    int x = threadIdx.x, y = threadIdx.y;
    #pragma unroll
    for (int i = 0; i < 32; i += 8)
        tile[y + i][x] = ib[(long)(c0 + y + i) * 4096 + s0 + x];
    __syncthreads();
    #pragma unroll
    for (int i = 0; i < 32; i += 8)
        ob[(long)(s0 + y + i) * DIMC + c0 + x] = tile[x][y + i];
}

// ---------------- weight transpose to fp16: in(R,C) -> out(C,R) ----------------
__global__ void k_transpose_w(const float* __restrict__ in, __half* __restrict__ out,
                              int R, int C) {
    __shared__ float tile[32][33];
    int r0 = blockIdx.y * 32, c0 = blockIdx.x * 32;
    int x = threadIdx.x, y = threadIdx.y;
    #pragma unroll
    for (int i = 0; i < 32; i += 8)
        tile[y + i][x] = in[(long)(r0 + y + i) * C + c0 + x];
    __syncthreads();
    #pragma unroll
    for (int i = 0; i < 32; i += 8)
        out[(long)(c0 + y + i) * R + r0 + x] = __float2half_rn(tile[x][y + i]);
}

// ---------------- block reduction ----------------
__device__ __forceinline__ float block_sum_256(float v, float* red) {
    int tid = threadIdx.x;
    #pragma unroll
    for (int o = 16; o > 0; o >>= 1) v += __shfl_xor_sync(0xffffffffu, v, o);
    if ((tid & 31) == 0) red[tid >> 5] = v;
    __syncthreads();
    float r = 0.f;
    if (tid < 8) {
        r = red[tid];
        #pragma unroll
        for (int o = 4; o > 0; o >>= 1) r += __shfl_xor_sync(0xffu, r, o);
        if (tid == 0) red[0] = r;
    }
    __syncthreads();
    r = red[0];
    __syncthreads();
    return r;
}

// ---------------- LN1 + window partition (fp16 output) ----------------
__global__ void k_ln1_window(const float* __restrict__ xnhwc,
                             const float* __restrict__ w, const float* __restrict__ bs,
                             __half* __restrict__ xwin) {
    __shared__ float red[8];
    int idx = blockIdx.x;
    int win = idx / NTOK, t = idx % NTOK;
    int b = win / 25, wrem = win % 25;
    int gr = (wrem / 5) * WS + t / WS;
    int gc = (wrem % 5) * WS + t % WS;
    __half* orow = xwin + (long)idx * DIMC;
    int tid = threadIdx.x;
    if (gr >= IMGH || gc >= IMGW) {
        for (int c = tid; c < DIMC; c += 256) orow[c] = __float2half_rn(0.f);
        return;
    }
    const float* irow = xnhwc + ((long)b * 4096 + gr * IMGW + gc) * DIMC;
    float v[3], s = 0.f, s2 = 0.f;
    #pragma unroll
    for (int i = 0; i < 3; i++) { float x = irow[tid + i * 256]; v[i] = x; s += x; s2 += x * x; }
    float tot = block_sum_256(s, red);
    float tot2 = block_sum_256(s2, red);
    float mu = tot * (1.f / DIMC);
    float rstd = rsqrtf(tot2 * (1.f / DIMC) - mu * mu + EPS_F);
    #pragma unroll
    for (int i = 0; i < 3; i++) {
        int c = tid + i * 256;
        orow[c] = __float2half_rn((v[i] - mu) * rstd * w[c] + bs[c]);
    }
}

// ---------------- fused: window unpartition + residual + LN2 ----------------
__global__ void k_scatter_ln2(const float* __restrict__ xnhwc, const float* __restrict__ proj,
                              const float* __restrict__ w, const float* __restrict__ bs,
                              float* __restrict__ x1, __half* __restrict__ yln) {
    __shared__ float red[8];
    int row = blockIdx.x;
    int b = row >> 12, sp = row & 4095;
    int r = sp >> 6, cw = sp & 63;
    int win = b * 25 + (r / WS) * 5 + (cw / WS);
    int t = (r % WS) * WS + (cw % WS);
    const float* prow = proj + ((long)win * NTOK + t) * DIMC;
    const float* xrow = xnhwc + (long)row * DIMC;
    float* orow = x1 + (long)row * DIMC;
    __half* lrow = yln + (long)row * DIMC;
    int tid = threadIdx.x;
    float v[3], s = 0.f, s2 = 0.f;
    #pragma unroll
    for (int i = 0; i < 3; i++) {
        int c = tid + i * 256;
        float x = xrow[c] + prow[c];
        orow[c] = x;
        v[i] = x; s += x; s2 += x * x;
    }
    float tot = block_sum_256(s, red);
    float tot2 = block_sum_256(s2, red);
    float mu = tot * (1.f / DIMC);
    float rstd = rsqrtf(tot2 * (1.f / DIMC) - mu * mu + EPS_F);
    #pragma unroll
    for (int i = 0; i < 3; i++) {
        int c = tid + i * 256;
        lrow[c] = __float2half_rn((v[i] - mu) * rstd * w[c] + bs[c]);
    }
}

// ---------------- fused windowed attention: 2 threads per query --------------
#define RELSTRIDE 65
#define QSTRIDE   17
#define ATTN_THREADS 392
#define ATTN_SMEM ((2*NTOK*HDIM + 2*27*RELSTRIDE + 2*NTOK*QSTRIDE) * sizeof(float))

__global__ void __launch_bounds__(ATTN_THREADS, 1)
k_attn(const float* __restrict__ qkv,
       const float* __restrict__ rel_pos_h,
       const float* __restrict__ rel_pos_w,
       __half* __restrict__ attnout) {
    extern __shared__ float smn[];
    float* Ks   = smn;
    float* Vs   = smn + NTOK * HDIM;
    float* RHsm = smn + 2 * NTOK * HDIM;
    float* RWsm = RHsm + 27 * RELSTRIDE;
    float* RHq  = RWsm + 27 * RELSTRIDE;
    float* RWq  = RHq + NTOK * QSTRIDE;

    int bidx = blockIdx.x;
    int win = bidx / HEADS, head = bidx % HEADS;
    int tid = threadIdx.x;
    const float* qkv_win = qkv + (long)win * NTOK * (3 * DIMC);

    for (int i = tid; i < NTOK * HDIM; i += ATTN_THREADS) {
        int t = i >> 6, d = i & 63;
        long base = (long)t * (3 * DIMC) + head * HDIM + d;
        Ks[i] = qkv_win[base + DIMC];
        Vs[i] = qkv_win[base + 2 * DIMC];
    }
    for (int i = tid; i < 27 * HDIM; i += ATTN_THREADS) {
        int r = i >> 6, d = i & 63;
        RHsm[r * RELSTRIDE + d] = rel_pos_h[i];
        RWsm[r * RELSTRIDE + d] = rel_pos_w[i];
    }
    __syncthreads();

    int q = tid >> 1, half = tid & 1;
    int qh = q / WS, qw = q % WS;
    unsigned pmask = ((tid & ~31) == 384) ? 0x000000ffu : 0xffffffffu;

    float qv[32];
    {
        const float* qp = qkv_win + (long)q * (3 * DIMC) + head * HDIM + half * 32;
        #pragma unroll
        for (int d = 0; d < 32; d++) qv[d] = qp[d];
    }

    #pragma unroll
    for (int kh = 0; kh < WS; kh++) {
        const float* ph = &RHsm[(qh - kh + WS - 1) * RELSTRIDE + half * 32];
        const float* pw = &RWsm[(qw - kh + WS - 1) * RELSTRIDE + half * 32];
        float sh = 0.f, sw = 0.f;
        #pragma unroll
        for (int d = 0; d < 32; d++) { sh = fmaf(qv[d], ph[d], sh); sw = fmaf(qv[d], pw[d], sw); }
        sh += __shfl_xor_sync(pmask, sh, 1);
        sw += __shfl_xor_sync(pmask, sw, 1);
        if (half == 0) { RHq[q * QSTRIDE + kh] = sh; RWq[q * QSTRIDE + kh] = sw; }
    }
    #pragma unroll
    for (int d = 0; d < 32; d++) qv[d] *= SCALE_F;
    __syncthreads();

    float m = -1e30f, l = 0.f;
    float acc[32];
    #pragma unroll
    for (int d = 0; d < 32; d++) acc[d] = 0.f;

    const float* rhq = RHq + q * QSTRIDE;
    const float* rwq = RWq + q * QSTRIDE;
    const float* KsH = Ks + half * 32;
    const float* VsH = Vs + half * 32;

    int kh = 0, kw = 0;
    for (int k = 0; k < NTOK; k++) {
        float part = 0.f;
        const float4* kp = (const float4*)(KsH + k * HDIM);
        #pragma unroll
        for (int d4 = 0; d4 < 8; d4++) {
            float4 kv = kp[d4];
            part = fmaf(qv[d4*4+0], kv.x, part); part = fmaf(qv[d4*4+1], kv.y, part);
            part = fmaf(qv[d4*4+2], kv.z, part); part = fmaf(qv[d4*4+3], kv.w, part);
        }
        part += __shfl_xor_sync(pmask, part, 1);
        float s = rhq[kh] + rwq[kw] + part;
        if (++kw == WS) { kw = 0; kh++; }
        float p;
        if (s > m) {
            float corr = __expf(m - s);
            l *= corr;
            #pragma unroll
            for (int d = 0; d < 32; d++) acc[d] *= corr;
            m = s; p = 1.f;
        } else {
            p = __expf(s - m);
        }
        l += p;
        const float4* vp = (const float4*)(VsH + k * HDIM);
        #pragma unroll
        for (int d4 = 0; d4 < 8; d4++) {
            float4 vv = vp[d4];
            acc[d4*4+0] = fmaf(p, vv.x, acc[d4*4+0]);
            acc[d4*4+1] = fmaf(p, vv.y, acc[d4*4+1]);
            acc[d4*4+2] = fmaf(p, vv.z, acc[d4*4+2]);
            acc[d4*4+3] = fmaf(p, vv.w, acc[d4*4+3]);
        }
    }
    float inv = 1.f / l;
    __half* op = attnout + ((long)win * NTOK + q) * DIMC + head * HDIM + half * 32;
    #pragma unroll
    for (int d = 0; d < 32; d++) op[d] = __float2half_rn(acc[d] * inv);
}

// ---------------- final: x1 + mlp_out, NHWC -> NCHW ----------------
__global__ void k_final(const float* __restrict__ x1, const float* __restrict__ y2,
                        float* __restrict__ out) {
    __shared__ float tile[32][33];
    int b = blockIdx.z, s0 = blockIdx.x * 32, c0 = blockIdx.y * 32;
    int x = threadIdx.x, y = threadIdx.y;
    #pragma unroll
    for (int i = 0; i < 32; i += 8) {
        long row = (long)b * 4096 + s0 + y + i;
        tile[y + i][x] = x1[row * DIMC + c0 + x] + y2[row * DIMC + c0 + x];
    }
    __syncthreads();
    #pragma unroll
    for (int i = 0; i < 32; i += 8)
        out[((long)b * DIMC + c0 + y + i) * 4096 + s0 + x] = tile[x][y + i];
}

// ---------------- launcher ----------------
extern "C" void kernel_launch(void* const* d_in, const int* in_sizes, int n_in,
                              void* d_out, int out_size) {
    const float* hidden = (const float*)d_in[0];
    const float* ln1_w = (const float*)d_in[1];
    const float* ln1_b = (const float*)d_in[2];
    const float* qkv_w = (const float*)d_in[3];
    const float* qkv_b = (const float*)d_in[4];
    const float* proj_w = (const float*)d_in[5];
    const float* proj_b = (const float*)d_in[6];
    const float* relh = (const float*)d_in[7];
    const float* relw = (const float*)d_in[8];
    const float* ln2_w = (const float*)d_in[9];
    const float* ln2_b = (const float*)d_in[10];
    const float* fc1_w = (const float*)d_in[11];
    const float* fc1_b = (const float*)d_in[12];
    const float* fc2_w = (const float*)d_in[13];
    const float* fc2_b = (const float*)d_in[14];
    float* out = (float*)d_out;

    float *xnhwc, *qkv, *proj, *x1, *y2;
    __half *xwin, *attno, *yln, *h1, *qkvT, *projT, *fc1T, *fc2T;
    cudaGetSymbolAddress((void**)&xnhwc, g_xnhwc);
    cudaGetSymbolAddress((void**)&xwin, g_xwin);
    cudaGetSymbolAddress((void**)&qkv, g_qkv);
    cudaGetSymbolAddress((void**)&attno, g_attno);
    cudaGetSymbolAddress((void**)&proj, g_proj);
    cudaGetSymbolAddress((void**)&x1, g_x1);
    cudaGetSymbolAddress((void**)&yln, g_yln);
    cudaGetSymbolAddress((void**)&h1, g_h1);
    cudaGetSymbolAddress((void**)&y2, g_y2);
    cudaGetSymbolAddress((void**)&qkvT, g_qkvT);
    cudaGetSymbolAddress((void**)&projT, g_projT);
    cudaGetSymbolAddress((void**)&fc1T, g_fc1T);
    cudaGetSymbolAddress((void**)&fc2T, g_fc2T);

    cudaFuncSetAttribute(k_attn, cudaFuncAttributeMaxDynamicSharedMemorySize, (int)ATTN_SMEM);
    cudaFuncSetAttribute(k_mma_gemm, cudaFuncAttributeMaxDynamicSharedMemorySize, GEMM_SMEM);

    dim3 tb(32, 8);
    // weight transposes -> fp16 K-major
    k_transpose_w<<<dim3(3 * DIMC / 32, DIMC / 32), tb>>>(qkv_w, qkvT, DIMC, 3 * DIMC);
    k_transpose_w<<<dim3(DIMC / 32, DIMC / 32), tb>>>(proj_w, projT, DIMC, DIMC);
    k_transpose_w<<<dim3(MLPD / 32, DIMC / 32), tb>>>(fc1_w, fc1T, DIMC, MLPD);
    k_transpose_w<<<dim3(DIMC / 32, MLPD / 32), tb>>>(fc2_w, fc2T, MLPD, DIMC);

    // 1) NCHW -> NHWC
    k_transpose_in<<<dim3(128, 24, BATCH), tb>>>(hidden, xnhwc);
    // 2) LN1 + window partition (fp16)
    k_ln1_window<<<NROWS_WIN, 256>>>(xnhwc, ln1_w, ln1_b, xwin);
    // 3) QKV: (19600,768) x (768,2304) -> fp32
    k_mma_gemm<<<dim3(3 * DIMC / 128, (NROWS_WIN + 127) / 128), 256, GEMM_SMEM>>>(
        xwin, qkvT, qkv_b, qkv, NROWS_WIN, 3 * DIMC, DIMC, 0, 0);
    // 4) attention (fp32 in, fp16 out)
    k_attn<<<NWIN * HEADS, ATTN_THREADS, ATTN_SMEM>>>(qkv, relh, relw, attno);
    // 5) proj: (19600,768) x (768,768) -> fp32
    k_mma_gemm<<<dim3(DIMC / 128, (NROWS_WIN + 127) / 128), 256, GEMM_SMEM>>>(
        attno, projT, proj_b, proj, NROWS_WIN, DIMC, DIMC, 0, 0);
    // 6) unpartition + residual + LN2 (x1 fp32, yln fp16)
    k_scatter_ln2<<<NROWS_IMG, 256>>>(xnhwc, proj, ln2_w, ln2_b, x1, yln);
    // 7) FC1 + GELU: (16384,768) x (768,3072) -> fp16
    k_mma_gemm<<<dim3(MLPD / 128, NROWS_IMG / 128), 256, GEMM_SMEM>>>(
        yln, fc1T, fc1_b, h1, NROWS_IMG, MLPD, DIMC, 1, 1);
    // 8) FC2: (16384,3072) x (3072,768) -> fp32
    k_mma_gemm<<<dim3(DIMC / 128, NROWS_IMG / 128), 256, GEMM_SMEM>>>(
        h1, fc2T, fc2_b, y2, NROWS_IMG, DIMC, MLPD, 0, 0);
    // 9) residual + NHWC -> NCHW
    k_final<<<dim3(128, 24, BATCH), tb>>>(x1, y2, out);
}

// round 11
// speedup vs baseline: 1.3379x; 1.0303x over previous
#include <cuda_runtime.h>
#include <cuda_fp16.h>
#include <math.h>
#include <stdint.h>

// ---------------- problem constants ----------------
#define DIMC    768
#define HEADS   12
#define HDIM    64
#define WS      14
#define NTOK    196
#define MLPD    3072
#define BATCH   4
#define IMGH    64
#define IMGW    64
#define NWIN    100
#define NROWS_WIN (NWIN*NTOK)        // 19600
#define NROWS_IMG (BATCH*IMGH*IMGW)  // 16384
#define SCALE_F 0.125f
#define EPS_F   1e-6f

// ---------------- scratch ----------------
__device__ float   g_xnhwc[BATCH*IMGH*IMGW*DIMC];
__device__ __half  g_xwin [NROWS_WIN*DIMC];
__device__ __half  g_qkv  [NROWS_WIN*3*DIMC];          // fp16 now (was fp32)
__device__ __half  g_attno[NROWS_WIN*DIMC];
__device__ float   g_proj [NROWS_WIN*DIMC];
__device__ float   g_x1   [NROWS_IMG*DIMC];
__device__ __half  g_yln  [NROWS_IMG*DIMC];
__device__ __half  g_h1   [NROWS_IMG*MLPD];
__device__ float   g_y2   [NROWS_IMG*DIMC];
// transposed weights (K-major B operands: Bt[n][k]), fp16
__device__ __half  g_qkvT [3*DIMC*DIMC];
__device__ __half  g_projT[DIMC*DIMC];
__device__ __half  g_fc1T [MLPD*DIMC];
__device__ __half  g_fc2T [DIMC*MLPD];

// ================= helpers =================
__device__ __forceinline__ uint32_t smem_u32(const void* p) {
    uint32_t a;
    asm("{ .reg .u64 t; cvta.to.shared.u64 t, %1; cvt.u32.u64 %0, t; }" : "=r"(a) : "l"(p));
    return a;
}
__device__ __forceinline__ void cp_async16(uint32_t dst, const void* src) {
    asm volatile("cp.async.cg.shared.global [%0], [%1], 16;" :: "r"(dst), "l"(src));
}
#define CP_COMMIT() asm volatile("cp.async.commit_group;" ::: "memory")
#define CP_WAIT(n)  asm volatile("cp.async.wait_group %0;" :: "n"(n) : "memory")

__device__ __forceinline__ void mma_f16(float* c, const uint32_t* a, const uint32_t* b) {
    asm volatile(
        "mma.sync.aligned.m16n8k16.row.col.f32.f16.f16.f32 "
        "{%0,%1,%2,%3}, {%4,%5,%6,%7}, {%8,%9}, {%0,%1,%2,%3};"
        : "+f"(c[0]), "+f"(c[1]), "+f"(c[2]), "+f"(c[3])
        : "r"(a[0]), "r"(a[1]), "r"(a[2]), "r"(a[3]), "r"(b[0]), "r"(b[1]));
}
__device__ __forceinline__ void ldmx4(uint32_t& r0, uint32_t& r1, uint32_t& r2, uint32_t& r3,
                                      uint32_t addr) {
    asm volatile("ldmatrix.sync.aligned.m8n8.x4.shared.b16 {%0,%1,%2,%3}, [%4];"
        : "=r"(r0), "=r"(r1), "=r"(r2), "=r"(r3) : "r"(addr));
}

// ================= fp16 mma.sync GEMM (R10-proven) =================
#define BM 128
#define BN 128
#define BKE 32
#define LDW 20
#define TBUF (BM*LDW)
#define GEMM_SMEM ((4*TBUF + 128) * 4)

__global__ void __launch_bounds__(256, 2)
k_mma_gemm(const __half* __restrict__ A, const __half* __restrict__ Bt,
           const float* __restrict__ bias, void* __restrict__ Cout,
           int M, int N, int K, int act, int outf16) {
    extern __shared__ float sm[];
    uint32_t* As = (uint32_t*)sm;
    uint32_t* Bs = As + 2*TBUF;
    float* sbias = sm + 4*TBUF;

    int tid = threadIdx.x, lane = tid & 31, wid = tid >> 5;
    int wm = wid >> 1, wn = wid & 1;
    int m0 = blockIdx.y * BM, n0 = blockIdx.x * BN;

    if (tid < 128) sbias[tid] = bias[n0 + tid];

    auto load_tile = [&](int kc, int bsel) {
        int k0 = kc * BKE;
        uint32_t* abuf = As + bsel * TBUF;
        uint32_t* bbuf = Bs + bsel * TBUF;
        #pragma unroll
        for (int it = 0; it < 2; it++) {
            int idx = tid + it * 256;
            int r = idx >> 2, c = idx & 3;
            int ar = m0 + r;
            const __half* asrc = A + (long)(ar < M ? ar : M - 1) * K + k0 + c * 8;
            cp_async16(smem_u32(abuf + r * LDW + c * 4), asrc);
            const __half* bsrc = Bt + (long)(n0 + r) * K + k0 + c * 8;
            cp_async16(smem_u32(bbuf + r * LDW + c * 4), bsrc);
        }
        CP_COMMIT();
    };

    int m8 = lane >> 3, r8 = lane & 7;
    uint32_t aoff[2], boff[4];
    #pragma unroll
    for (int mt = 0; mt < 2; mt++)
        aoff[mt] = (uint32_t)((wm * 32 + mt * 16 + (m8 & 1) * 8 + r8) * LDW + (m8 >> 1) * 4);
    #pragma unroll
    for (int p = 0; p < 4; p++)
        boff[p] = (uint32_t)((wn * 64 + p * 16 + (m8 >> 1) * 8 + r8) * LDW + (m8 & 1) * 4);
    uint32_t a_base = smem_u32(As);
    uint32_t b_base = smem_u32(Bs);

    float acc[2][8][4];
    #pragma unroll
    for (int mt = 0; mt < 2; mt++)
        #pragma unroll
        for (int nt = 0; nt < 8; nt++)
            #pragma unroll
            for (int j = 0; j < 4; j++) acc[mt][nt][j] = 0.f;

    const int NKC = K / BKE;
    load_tile(0, 0);
    for (int i = 0; i < NKC; i++) {
        int cur = i & 1;
        if (i + 1 < NKC) { load_tile(i + 1, cur ^ 1); CP_WAIT(1); }
        else             { CP_WAIT(0); }
        __syncthreads();
        uint32_t ab = a_base + cur * (TBUF * 4);
        uint32_t bb = b_base + cur * (TBUF * 4);
        #pragma unroll
        for (int ks = 0; ks < 2; ks++) {
            uint32_t af[2][4], bf[8][2];
            #pragma unroll
            for (int mt = 0; mt < 2; mt++)
                ldmx4(af[mt][0], af[mt][1], af[mt][2], af[mt][3],
                      ab + (aoff[mt] + ks * 8) * 4);
            #pragma unroll
            for (int p = 0; p < 4; p++)
                ldmx4(bf[2*p][0], bf[2*p][1], bf[2*p+1][0], bf[2*p+1][1],
                      bb + (boff[p] + ks * 8) * 4);
            #pragma unroll
            for (int mt = 0; mt < 2; mt++)
                #pragma unroll
                for (int nt = 0; nt < 8; nt++)
                    mma_f16(acc[mt][nt], af[mt], bf[nt]);
        }
        __syncthreads();
    }

    int rb = m0 + wm * 32 + (lane >> 2);
    int cb = wn * 64 + 2 * (lane & 3);
    #pragma unroll
    for (int mt = 0; mt < 2; mt++) {
        int r0 = rb + mt * 16, r1 = r0 + 8;
        #pragma unroll
        for (int nt = 0; nt < 8; nt++) {
            int cc = cb + nt * 8;
            float v0 = acc[mt][nt][0] + sbias[cc];
            float v1 = acc[mt][nt][1] + sbias[cc + 1];
            float v2 = acc[mt][nt][2] + sbias[cc];
            float v3 = acc[mt][nt][3] + sbias[cc + 1];
            if (act == 1) {
                v0 = 0.5f * v0 * (1.0f + erff(v0 * 0.70710678118654752f));
                v1 = 0.5f * v1 * (1.0f + erff(v1 * 0.70710678118654752f));
                v2 = 0.5f * v2 * (1.0f + erff(v2 * 0.70710678118654752f));
                v3 = 0.5f * v3 * (1.0f + erff(v3 * 0.70710678118654752f));
            }
            if (outf16) {
                __half* C = (__half*)Cout;
                if (r0 < M) *(__half2*)(C + (long)r0 * N + n0 + cc) = __floats2half2_rn(v0, v1);
                if (r1 < M) *(__half2*)(C + (long)r1 * N + n0 + cc) = __floats2half2_rn(v2, v3);
            } else {
                float* C = (float*)Cout;
                if (r0 < M) *(float2*)(C + (long)r0 * N + n0 + cc) = make_float2(v0, v1);
                if (r1 < M) *(float2*)(C + (long)r1 * N + n0 + cc) = make_float2(v2, v3);
            }
        }
    }
}

// ---------------- NCHW -> NHWC transpose ----------------
__global__ void k_transpose_in(const float* __restrict__ in, float* __restrict__ out) {
    __shared__ float tile[32][33];
    int b = blockIdx.z, c0 = blockIdx.y * 32, s0 = blockIdx.x * 32;
    const float* ib = in + (long)b * DIMC * 4096;
    float* ob = out + (long)b * 4096 * DIMC;
    int x = threadIdx.x, y = threadIdx.y;
    #pragma unroll
    for (int i = 0; i < 32; i += 8)
        tile[y + i][x] = ib[(long)(c0 + y + i) * 4096 + s0 + x];
    __syncthreads();
    #pragma unroll
    for (int i = 0; i < 32; i += 8)
        ob[(long)(s0 + y + i) * DIMC + c0 + x] = tile[x][y + i];
}

// ---------------- weight transpose to fp16 ----------------
__global__ void k_transpose_w(const float* __restrict__ in, __half* __restrict__ out,
                              int R, int C) {
    __shared__ float tile[32][33];
    int r0 = blockIdx.y * 32, c0 = blockIdx.x * 32;
    int x = threadIdx.x, y = threadIdx.y;
    #pragma unroll
    for (int i = 0; i < 32; i += 8)
        tile[y + i][x] = in[(long)(r0 + y + i) * C + c0 + x];
    __syncthreads();
    #pragma unroll
    for (int i = 0; i < 32; i += 8)
        out[(long)(c0 + y + i) * R + r0 + x] = __float2half_rn(tile[x][y + i]);
}

// ---------------- block reduction ----------------
__device__ __forceinline__ float block_sum_256(float v, float* red) {
    int tid = threadIdx.x;
    #pragma unroll
    for (int o = 16; o > 0; o >>= 1) v += __shfl_xor_sync(0xffffffffu, v, o);
    if ((tid & 31) == 0) red[tid >> 5] = v;
    __syncthreads();
    float r = 0.f;
    if (tid < 8) {
        r = red[tid];
        #pragma unroll
        for (int o = 4; o > 0; o >>= 1) r += __shfl_xor_sync(0xffu, r, o);
        if (tid == 0) red[0] = r;
    }
    __syncthreads();
    r = red[0];
    __syncthreads();
    return r;
}

// ---------------- LN1 + window partition (fp16 output) ----------------
__global__ void k_ln1_window(const float* __restrict__ xnhwc,
                             const float* __restrict__ w, const float* __restrict__ bs,
                             __half* __restrict__ xwin) {
    __shared__ float red[8];
    int idx = blockIdx.x;
    int win = idx / NTOK, t = idx % NTOK;
    int b = win / 25, wrem = win % 25;
    int gr = (wrem / 5) * WS + t / WS;
    int gc = (wrem % 5) * WS + t % WS;
    __half* orow = xwin + (long)idx * DIMC;
    int tid = threadIdx.x;
    if (gr >= IMGH || gc >= IMGW) {
        for (int c = tid; c < DIMC; c += 256) orow[c] = __float2half_rn(0.f);
        return;
    }
    const float* irow = xnhwc + ((long)b * 4096 + gr * IMGW + gc) * DIMC;
    float v[3], s = 0.f, s2 = 0.f;
    #pragma unroll
    for (int i = 0; i < 3; i++) { float x = irow[tid + i * 256]; v[i] = x; s += x; s2 += x * x; }
    float tot = block_sum_256(s, red);
    float tot2 = block_sum_256(s2, red);
    float mu = tot * (1.f / DIMC);
    float rstd = rsqrtf(tot2 * (1.f / DIMC) - mu * mu + EPS_F);
    #pragma unroll
    for (int i = 0; i < 3; i++) {
        int c = tid + i * 256;
        orow[c] = __float2half_rn((v[i] - mu) * rstd * w[c] + bs[c]);
    }
}

// ---------------- fused: window unpartition + residual + LN2 ----------------
__global__ void k_scatter_ln2(const float* __restrict__ xnhwc, const float* __restrict__ proj,
                              const float* __restrict__ w, const float* __restrict__ bs,
                              float* __restrict__ x1, __half* __restrict__ yln) {
    __shared__ float red[8];
    int row = blockIdx.x;
    int b = row >> 12, sp = row & 4095;
    int r = sp >> 6, cw = sp & 63;
    int win = b * 25 + (r / WS) * 5 + (cw / WS);
    int t = (r % WS) * WS + (cw % WS);
    const float* prow = proj + ((long)win * NTOK + t) * DIMC;
    const float* xrow = xnhwc + (long)row * DIMC;
    float* orow = x1 + (long)row * DIMC;
    __half* lrow = yln + (long)row * DIMC;
    int tid = threadIdx.x;
    float v[3], s = 0.f, s2 = 0.f;
    #pragma unroll
    for (int i = 0; i < 3; i++) {
        int c = tid + i * 256;
        float x = xrow[c] + prow[c];
        orow[c] = x;
        v[i] = x; s += x; s2 += x * x;
    }
    float tot = block_sum_256(s, red);
    float tot2 = block_sum_256(s2, red);
    float mu = tot * (1.f / DIMC);
    float rstd = rsqrtf(tot2 * (1.f / DIMC) - mu * mu + EPS_F);
    #pragma unroll
    for (int i = 0; i < 3; i++) {
        int c = tid + i * 256;
        lrow[c] = __float2half_rn((v[i] - mu) * rstd * w[c] + bs[c]);
    }
}

// ---------------- fused windowed attention: 2 threads per query --------------
// qkv is fp16; K/V converted to fp32 smem once; inner loop unchanged fp32.
#define RELSTRIDE 65
#define QSTRIDE   17
#define ATTN_THREADS 392
#define ATTN_SMEM ((2*NTOK*HDIM + 2*27*RELSTRIDE + 2*NTOK*QSTRIDE) * sizeof(float))

__global__ void __launch_bounds__(ATTN_THREADS, 1)
k_attn(const __half* __restrict__ qkv,
       const float* __restrict__ rel_pos_h,
       const float* __restrict__ rel_pos_w,
       __half* __restrict__ attnout) {
    extern __shared__ float smn[];
    float* Ks   = smn;
    float* Vs   = smn + NTOK * HDIM;
    float* RHsm = smn + 2 * NTOK * HDIM;
    float* RWsm = RHsm + 27 * RELSTRIDE;
    float* RHq  = RWsm + 27 * RELSTRIDE;
    float* RWq  = RHq + NTOK * QSTRIDE;

    int bidx = blockIdx.x;
    int win = bidx / HEADS, head = bidx % HEADS;
    int tid = threadIdx.x;
    const __half* qkv_win = qkv + (long)win * NTOK * (3 * DIMC);

    // fill K/V smem (fp16 -> fp32), vectorized 8 halves per iteration
    for (int i = tid; i < NTOK * 8; i += ATTN_THREADS) {
        int t = i >> 3, c = i & 7;
        const __half2* ksrc = (const __half2*)(qkv_win + (long)t * (3 * DIMC) + DIMC + head * HDIM + c * 8);
        const __half2* vsrc = (const __half2*)(qkv_win + (long)t * (3 * DIMC) + 2 * DIMC + head * HDIM + c * 8);
        float* kdst = Ks + t * HDIM + c * 8;
        float* vdst = Vs + t * HDIM + c * 8;
        #pragma unroll
        for (int j = 0; j < 4; j++) {
            float2 kf = __half22float2(ksrc[j]);
            float2 vf = __half22float2(vsrc[j]);
            kdst[2*j] = kf.x; kdst[2*j+1] = kf.y;
            vdst[2*j] = vf.x; vdst[2*j+1] = vf.y;
        }
    }
    for (int i = tid; i < 27 * HDIM; i += ATTN_THREADS) {
        int r = i >> 6, d = i & 63;
        RHsm[r * RELSTRIDE + d] = rel_pos_h[i];
        RWsm[r * RELSTRIDE + d] = rel_pos_w[i];
    }
    __syncthreads();

    int q = tid >> 1, half = tid & 1;
    int qh = q / WS, qw = q % WS;
    unsigned pmask = ((tid & ~31) == 384) ? 0x000000ffu : 0xffffffffu;

    float qv[32];
    {
        const __half* qp = qkv_win + (long)q * (3 * DIMC) + head * HDIM + half * 32;
        #pragma unroll
        for (int d = 0; d < 32; d += 2) {
            float2 f = __half22float2(*(const __half2*)(qp + d));
            qv[d] = f.x; qv[d+1] = f.y;
        }
    }

    #pragma unroll
    for (int kh = 0; kh < WS; kh++) {
        const float* ph = &RHsm[(qh - kh + WS - 1) * RELSTRIDE + half * 32];
        const float* pw = &RWsm[(qw - kh + WS - 1) * RELSTRIDE + half * 32];
        float sh = 0.f, sw = 0.f;
        #pragma unroll
        for (int d = 0; d < 32; d++) { sh = fmaf(qv[d], ph[d], sh); sw = fmaf(qv[d], pw[d], sw); }
        sh += __shfl_xor_sync(pmask, sh, 1);
        sw += __shfl_xor_sync(pmask, sw, 1);
        if (half == 0) { RHq[q * QSTRIDE + kh] = sh; RWq[q * QSTRIDE + kh] = sw; }
    }
    #pragma unroll
    for (int d = 0; d < 32; d++) qv[d] *= SCALE_F;
    __syncthreads();

    float m = -1e30f, l = 0.f;
    float acc[32];
    #pragma unroll
    for (int d = 0; d < 32; d++) acc[d] = 0.f;

    const float* rhq = RHq + q * QSTRIDE;
    const float* rwq = RWq + q * QSTRIDE;
    const float* KsH = Ks + half * 32;
    const float* VsH = Vs + half * 32;

    int kh = 0, kw = 0;
    for (int k = 0; k < NTOK; k++) {
        float part = 0.f;
        const float4* kp = (const float4*)(KsH + k * HDIM);
        #pragma unroll
        for (int d4 = 0; d4 < 8; d4++) {
            float4 kv = kp[d4];
            part = fmaf(qv[d4*4+0], kv.x, part); part = fmaf(qv[d4*4+1], kv.y, part);
            part = fmaf(qv[d4*4+2], kv.z, part); part = fmaf(qv[d4*4+3], kv.w, part);
        }
        part += __shfl_xor_sync(pmask, part, 1);
        float s = rhq[kh] + rwq[kw] + part;
        if (++kw == WS) { kw = 0; kh++; }
        float p;
        if (s > m) {
            float corr = __expf(m - s);
            l *= corr;
            #pragma unroll
            for (int d = 0; d < 32; d++) acc[d] *= corr;
            m = s; p = 1.f;
        } else {
            p = __expf(s - m);
        }
        l += p;
        const float4* vp = (const float4*)(VsH + k * HDIM);
        #pragma unroll
        for (int d4 = 0; d4 < 8; d4++) {
            float4 vv = vp[d4];
            acc[d4*4+0] = fmaf(p, vv.x, acc[d4*4+0]);
            acc[d4*4+1] = fmaf(p, vv.y, acc[d4*4+1]);
            acc[d4*4+2] = fmaf(p, vv.z, acc[d4*4+2]);
            acc[d4*4+3] = fmaf(p, vv.w, acc[d4*4+3]);
        }
    }
    float inv = 1.f / l;
    __half* op = attnout + ((long)win * NTOK + q) * DIMC + head * HDIM + half * 32;
    #pragma unroll
    for (int d = 0; d < 32; d++) op[d] = __float2half_rn(acc[d] * inv);
}

// ---------------- final: x1 + mlp_out, NHWC -> NCHW ----------------
__global__ void k_final(const float* __restrict__ x1, const float* __restrict__ y2,
                        float* __restrict__ out) {
    __shared__ float tile[32][33];
    int b = blockIdx.z, s0 = blockIdx.x * 32, c0 = blockIdx.y * 32;
    int x = threadIdx.x, y = threadIdx.y;
    #pragma unroll
    for (int i = 0; i < 32; i += 8) {
        long row = (long)b * 4096 + s0 + y + i;
        tile[y + i][x] = x1[row * DIMC + c0 + x] + y2[row * DIMC + c0 + x];
    }
    __syncthreads();
    #pragma unroll
    for (int i = 0; i < 32; i += 8)
        out[((long)b * DIMC + c0 + y + i) * 4096 + s0 + x] = tile[x][y + i];
}

// ---------------- launcher ----------------
extern "C" void kernel_launch(void* const* d_in, const int* in_sizes, int n_in,
                              void* d_out, int out_size) {
    const float* hidden = (const float*)d_in[0];
    const float* ln1_w = (const float*)d_in[1];
    const float* ln1_b = (const float*)d_in[2];
    const float* qkv_w = (const float*)d_in[3];
    const float* qkv_b = (const float*)d_in[4];
    const float* proj_w = (const float*)d_in[5];
    const float* proj_b = (const float*)d_in[6];
    const float* relh = (const float*)d_in[7];
    const float* relw = (const float*)d_in[8];
    const float* ln2_w = (const float*)d_in[9];
    const float* ln2_b = (const float*)d_in[10];
    const float* fc1_w = (const float*)d_in[11];
    const float* fc1_b = (const float*)d_in[12];
    const float* fc2_w = (const float*)d_in[13];
    const float* fc2_b = (const float*)d_in[14];
    float* out = (float*)d_out;

    float *xnhwc, *proj, *x1, *y2;
    __half *xwin, *qkv, *attno, *yln, *h1, *qkvT, *projT, *fc1T, *fc2T;
    cudaGetSymbolAddress((void**)&xnhwc, g_xnhwc);
    cudaGetSymbolAddress((void**)&xwin, g_xwin);
    cudaGetSymbolAddress((void**)&qkv, g_qkv);
    cudaGetSymbolAddress((void**)&attno, g_attno);
    cudaGetSymbolAddress((void**)&proj, g_proj);
    cudaGetSymbolAddress((void**)&x1, g_x1);
    cudaGetSymbolAddress((void**)&yln, g_yln);
    cudaGetSymbolAddress((void**)&h1, g_h1);
    cudaGetSymbolAddress((void**)&y2, g_y2);
    cudaGetSymbolAddress((void**)&qkvT, g_qkvT);
    cudaGetSymbolAddress((void**)&projT, g_projT);
    cudaGetSymbolAddress((void**)&fc1T, g_fc1T);
    cudaGetSymbolAddress((void**)&fc2T, g_fc2T);

    cudaFuncSetAttribute(k_attn, cudaFuncAttributeMaxDynamicSharedMemorySize, (int)ATTN_SMEM);
    cudaFuncSetAttribute(k_mma_gemm, cudaFuncAttributeMaxDynamicSharedMemorySize, GEMM_SMEM);

    dim3 tb(32, 8);
    // launch order arranged so ncu (skip 5, capture 1) profiles the QKV GEMM (#6)
    // 1) qkv weight transpose
    k_transpose_w<<<dim3(3 * DIMC / 32, DIMC / 32), tb>>>(qkv_w, qkvT, DIMC, 3 * DIMC);
    // 2) NCHW -> NHWC
    k_transpose_in<<<dim3(128, 24, BATCH), tb>>>(hidden, xnhwc);
    // 3) LN1 + window partition (fp16)
    k_ln1_window<<<NROWS_WIN, 256>>>(xnhwc, ln1_w, ln1_b, xwin);
    // 4) proj weight transpose
    k_transpose_w<<<dim3(DIMC / 32, DIMC / 32), tb>>>(proj_w, projT, DIMC, DIMC);
    // 5) fc1 weight transpose
    k_transpose_w<<<dim3(MLPD / 32, DIMC / 32), tb>>>(fc1_w, fc1T, DIMC, MLPD);
    // 6) QKV GEMM: (19600,768) x (768,2304) -> fp16   [ncu profiles this one]
    k_mma_gemm<<<dim3(3 * DIMC / 128, (NROWS_WIN + 127) / 128), 256, GEMM_SMEM>>>(
        xwin, qkvT, qkv_b, qkv, NROWS_WIN, 3 * DIMC, DIMC, 0, 1);
    // 7) fc2 weight transpose
    k_transpose_w<<<dim3(DIMC / 32, MLPD / 32), tb>>>(fc2_w, fc2T, MLPD, DIMC);
    // 8) attention (fp16 in, fp16 out)
    k_attn<<<NWIN * HEADS, ATTN_THREADS, ATTN_SMEM>>>(qkv, relh, relw, attno);
    // 9) proj: (19600,768) x (768,768) -> fp32
    k_mma_gemm<<<dim3(DIMC / 128, (NROWS_WIN + 127) / 128), 256, GEMM_SMEM>>>(
        attno, projT, proj_b, proj, NROWS_WIN, DIMC, DIMC, 0, 0);
    // 10) unpartition + residual + LN2 (x1 fp32, yln fp16)
    k_scatter_ln2<<<NROWS_IMG, 256>>>(xnhwc, proj, ln2_w, ln2_b, x1, yln);
    // 11) FC1 + GELU: (16384,768) x (768,3072) -> fp16
    k_mma_gemm<<<dim3(MLPD / 128, NROWS_IMG / 128), 256, GEMM_SMEM>>>(
        yln, fc1T, fc1_b, h1, NROWS_IMG, MLPD, DIMC, 1, 1);
    // 12) FC2: (16384,3072) x (3072,768) -> fp32
    k_mma_gemm<<<dim3(DIMC / 128, NROWS_IMG / 128), 256, GEMM_SMEM>>>(
        h1, fc2T, fc2_b, y2, NROWS_IMG, DIMC, MLPD, 0, 0);
    // 13) residual + NHWC -> NCHW
    k_final<<<dim3(128, 24, BATCH), tb>>>(x1, y2, out);
}